// round 16
// baseline (speedup 1.0000x reference)
#include <cuda_runtime.h>
#include <cuda_bf16.h>
#include <math.h>

// Problem constants
#define BB 128
#define TT 256
#define DD 256
#define HH 256

#define NBLK 128        // 16 groups x (4 layer-1 CTAs + 4 layer-2 CTAs)
#define NGRP 16
#define NTH  512

typedef unsigned long long ull;

// ---------------- packed f32x2 helpers ----------------
__device__ __forceinline__ ull pack2(float lo, float hi) {
    ull r; asm("mov.b64 %0, {%1, %2};" : "=l"(r) : "f"(lo), "f"(hi)); return r;
}
__device__ __forceinline__ void unpack2(float& lo, float& hi, ull v) {
    asm("mov.b64 {%0, %1}, %2;" : "=f"(lo), "=f"(hi) : "l"(v));
}
__device__ __forceinline__ ull fma2(ull a, ull b, ull c) {
    ull d; asm("fma.rn.f32x2 %0, %1, %2, %3;" : "=l"(d) : "l"(a), "l"(b), "l"(c));
    return d;
}

// ---------------- device scratch ----------------
__device__ float g_pre1[TT * BB * HH];        // pre1[t][b][h] row-major (incl b1)
__device__ float g_P1[2][NGRP][4][2048];      // Whh1 partials  [ring2][grp][src][row*256+col]
__device__ float g_P [4][NGRP][4][2048];      // Wih2 partials  [ring4][grp][src][row*256+col]
__device__ float g_P2[2][NGRP][4][2048];      // Whh2 partials  [ring2][grp][src][row*256+col]
__device__ float g_h2rm[BB * HH];             // final forward h2, row-major
__device__ float g_h1bk[BB * HH];
__device__ float g_h2bk[BB * HH];
__device__ unsigned g_f1[NGRP * 32];          // partial1 ready
__device__ unsigned g_f1p[NGRP * 32];         // P ready
__device__ unsigned g_f2[NGRP * 32];          // partial2 ready / L2 step done

// ---------------- reset kernel ----------------
__global__ void k_reset() {
    unsigned i = blockIdx.x * blockDim.x + threadIdx.x;
    if (i < NGRP * 32) { g_f1[i] = 0u; g_f1p[i] = 0u; g_f2[i] = 0u; }
}

// ---------------- release/acquire flag ops ----------------
__device__ __forceinline__ void signal(unsigned* p) {
    __syncthreads();
    if (threadIdx.x == 0)
        asm volatile("red.release.gpu.add.u32 [%0], 1;" :: "l"(p) : "memory");
}
__device__ __forceinline__ void waitflag(unsigned* p, unsigned t) {
    if (threadIdx.x == 0) {
        unsigned v;
        do { asm volatile("ld.acquire.gpu.u32 %0, [%1];" : "=r"(v) : "l"(p) : "memory");
        } while (v < t);
    }
    __syncthreads();
}

// ---------------- cp.async helpers ----------------
__device__ __forceinline__ unsigned smem_u32(const void* p) {
    unsigned a;
    asm("{ .reg .u64 t; cvta.to.shared.u64 t, %1; cvt.u32.u64 %0, t; }"
        : "=r"(a) : "l"(p));
    return a;
}
__device__ __forceinline__ void cpa16(unsigned saddr, const float* gaddr) {
    asm volatile("cp.async.cg.shared.global [%0], [%1], 16;"
                 :: "r"(saddr), "l"(gaddr) : "memory");
}
#define CPA_COMMIT()  asm volatile("cp.async.commit_group;" ::: "memory")
#define CPA_WAIT(n)   asm volatile("cp.async.wait_group %0;" :: "n"(n) : "memory")

// 64k x 256col weight slice -> smem sW[k*256 + j]; Wbase points at slice origin
__device__ __forceinline__ void load_slice(unsigned u_sW, const float* __restrict__ Wbase,
                                           int tid) {
#pragma unroll
    for (int i = 0; i < 8; i++) {
        int chunk = tid + i * NTH;          // 0..4095 float4 chunks
        int k = chunk >> 6;
        int j4 = (chunk & 63) * 4;
        cpa16(u_sW + (unsigned)chunk * 16, Wbase + (long)k * HH + j4);
    }
}

// ---------------- generic 64x64 register-blocked fp32 GEMM tile (FFMA2) ----------------
__device__ __forceinline__ void gemm64_body(
    const float* __restrict__ A, long lda,
    const float* __restrict__ A2, int ksplit, long lda2,
    const float* __restrict__ W, long ldw, int wtrans,
    const float* __restrict__ bias,
    float* __restrict__ C, long ldc,
    int K, int row0, int col0, int act,
    float* sA, float* sW)
{
    const int tid = threadIdx.x;
    const int tx = tid & 15;
    const int ty = tid >> 4;
    ull accp[4][2];
#pragma unroll
    for (int i = 0; i < 4; i++) { accp[i][0] = 0ull; accp[i][1] = 0ull; }

#pragma unroll 1
    for (int k0 = 0; k0 < K; k0 += 64) {
        const float* Ak = A; long ldak = lda; int kb = k0;
        if (A2 != nullptr && k0 >= ksplit) { Ak = A2; ldak = lda2; kb = k0 - ksplit; }

        __syncthreads();
#pragma unroll
        for (int p = 0; p < 4; p++) {
            int i = p * 256 + tid;
            int rr = i >> 4;
            int k4 = i & 15;
            float4 v = *(const float4*)(Ak + (long)(row0 + rr) * ldak + kb + k4 * 4);
            *(float4*)(sA + rr * 72 + k4 * 4) = v;
        }
        if (!wtrans) {
#pragma unroll
            for (int p = 0; p < 16; p++) {
                int i = p * 256 + tid;
                int kk = i >> 6, cc = i & 63;
                sW[kk * 72 + cc] = W[(long)(k0 + kk) * ldw + col0 + cc];
            }
        } else {
#pragma unroll
            for (int p = 0; p < 16; p++) {
                int i = p * 256 + tid;
                int kk = i & 63, cc = i >> 6;
                sW[kk * 72 + cc] = W[(long)(col0 + cc) * ldw + k0 + kk];
            }
        }
        __syncthreads();

#pragma unroll
        for (int k = 0; k < 64; k++) {
            ulonglong2 wv = *(const ulonglong2*)(sW + k * 72 + tx * 4);
#pragma unroll
            for (int i = 0; i < 4; i++) {
                float a = sA[(ty * 4 + i) * 72 + k];
                ull ap = pack2(a, a);
                accp[i][0] = fma2(ap, wv.x, accp[i][0]);
                accp[i][1] = fma2(ap, wv.y, accp[i][1]);
            }
        }
    }

#pragma unroll
    for (int i = 0; i < 4; i++) {
        float v0, v1, v2, v3;
        unpack2(v0, v1, accp[i][0]);
        unpack2(v2, v3, accp[i][1]);
        float vv[4] = {v0, v1, v2, v3};
#pragma unroll
        for (int j = 0; j < 4; j++) {
            int rr = row0 + ty * 4 + i;
            int cc = col0 + tx * 4 + j;
            float v = vv[j] + bias[cc];
            if (act) v = tanhf(v);
            C[(long)rr * ldc + cc] = v;
        }
    }
}

// ---------------- K1: precompute pre1[t] ----------------
__global__ __launch_bounds__(256) void k_pre(
    const float* __restrict__ x, const float* __restrict__ Wih_f,
    const float* __restrict__ b_f)
{
    __shared__ float sA[64 * 72];
    __shared__ float sW[64 * 72];
    int t = blockIdx.y;
    int tile = blockIdx.x;
    int row0 = (tile >> 2) * 64;
    int col0 = (tile & 3) * 64;
    gemm64_body(x + (long)t * DD, (long)TT * DD,
                nullptr, 1 << 30, 0,
                Wih_f + (long)t * DD * HH, HH, 0,
                b_f + (long)t * HH,
                g_pre1 + (long)t * BB * HH, HH,
                DD, row0, col0, /*act=*/0, sA, sW);
}

// ================= K2: k-split ownership + wait-hiding reorder =================
// vs R15 (1317us): identical data layout & flag protocol. ONLY the ordering
// changed: L1 unfuses its two dots — dotA (Whh1) -> signal f1 -> dotP (Wih2)
// runs WHILE the f1 flags propagate -> wait f1 is then (mostly) free.
// L2 gathers the P terms (flag set a step earlier) before waiting on its
// peers' f2, hiding that wait under the L2 loads.

// smem (floats): hsO 512 | sW0 16384 | sW1 16384 | sWI 16384
#define SMEM_SEQ_BYTES ((512 + 16384 * 3) * 4)

__global__ __launch_bounds__(NTH, 1)
void k_seq(const float* __restrict__ Wih_f, const float* __restrict__ Whh_f,
           const float* __restrict__ b_f)
{
    extern __shared__ float dyn[];
    float* hsO = dyn;                   // own h cols [kl*8 + row], 64x8
    float* W0  = dyn + 512;             // Whh slice double buffer 0
    float* W1  = W0 + 16384;            // Whh slice double buffer 1
    float* WI  = W1 + 16384;            // L1 only: Wih2 slice (single)
    const unsigned u_W0 = smem_u32(W0);
    const unsigned u_W1 = smem_u32(W1);
    const unsigned u_WI = smem_u32(WI);

    const int tid = threadIdx.x;
    const int ph = tid >> 8;                             // dot: rows 4ph..4ph+3
    const int pj = tid & 255;                            // dot: output col
    const int rowS = tid >> 6;                           // sum: row 0..7
    const int cS = tid & 63;                             // sum: own col 0..63
    const int grp = blockIdx.x >> 3;
    const int sub = blockIdx.x & 7;
    const int layer = sub >> 2;
    const int r = sub & 3;                               // own cols 64r..64r+63
    const int row_base = grp * 8;
    const int rmS = (row_base + rowS) * HH + 64 * r + cS;  // row-major slot
    unsigned* f1  = &g_f1[grp * 32];
    unsigned* f1p = &g_f1p[grp * 32];
    unsigned* f2  = &g_f2[grp * 32];

    const float* Whh1 = Whh_f;
    const float* Wih2 = Wih_f + (long)TT * DD * HH;
    const float* Whh2 = Whh_f + (long)TT * HH * HH;
    const float* b2   = b_f + (long)TT * HH;
    const long sliceoff = (long)(64 * r) * HH;           // slice row origin

    if (layer == 0) {
        // ============ layer 1: own-cols recurrence, wait hidden by P dot ============
        load_slice(u_W0, Whh1 + sliceoff, tid);          // Whh1[0] slice
        CPA_COMMIT();
        load_slice(u_WI, Wih2 + sliceoff, tid);          // Wih2[0] slice
        CPA_COMMIT();
        for (int i = tid; i < 512; i += NTH) hsO[i] = 0.f;   // h1[-1] own cols = 0
        float pre = __ldg(g_pre1 + rmS);

#pragma unroll 1
        for (int t = 0; t < TT; t++) {
            const int tn = (t < TT - 1) ? t + 1 : t;

            // top: P-ring backpressure (rarely binds) + weight arrival
            if (t >= 2) waitflag(f2, 4u * (unsigned)(t - 2));
            CPA_WAIT(0);
            __syncthreads();                              // weights + hsO visible
            load_slice(((t + 1) & 1) ? u_W1 : u_W0,       // Whh1[t+1] (other buf)
                       Whh1 + (long)tn * HH * HH + sliceoff, tid);
            CPA_COMMIT();

            // ---- dot A: partial1 = hsO @ Whh1[t]slice ----
            const float* sWA = (t & 1) ? W1 : W0;
            ull aA0 = 0ull, aA1 = 0ull;
#pragma unroll
            for (int kl = 0; kl < 64; kl++) {
                ulonglong2 hv = *(const ulonglong2*)(hsO + kl * 8 + 4 * ph);
                float wA = sWA[kl * 256 + pj];
                ull wAp = pack2(wA, wA);
                aA0 = fma2(hv.x, wAp, aA0);
                aA1 = fma2(hv.y, wAp, aA1);
            }
            {   // store partial1[t] and announce immediately
                float q0, q1, q2, q3;
                unpack2(q0, q1, aA0);
                unpack2(q2, q3, aA1);
                float* d = &g_P1[t & 1][grp][r][0];
                __stcg(d + (ph * 4 + 0) * 256 + pj, q0);
                __stcg(d + (ph * 4 + 1) * 256 + pj, q1);
                __stcg(d + (ph * 4 + 2) * 256 + pj, q2);
                __stcg(d + (ph * 4 + 3) * 256 + pj, q3);
            }
            signal(f1);

            // ---- dot P: hsO @ Wih2[t-1]slice — hides f1 propagation ----
            if (t > 0) {
                ull aI0 = 0ull, aI1 = 0ull;
#pragma unroll
                for (int kl = 0; kl < 64; kl++) {
                    ulonglong2 hv = *(const ulonglong2*)(hsO + kl * 8 + 4 * ph);
                    float wI = WI[kl * 256 + pj];
                    ull wIp = pack2(wI, wI);
                    aI0 = fma2(hv.x, wIp, aI0);
                    aI1 = fma2(hv.y, wIp, aI1);
                }
                float q0, q1, q2, q3;
                unpack2(q0, q1, aI0);
                unpack2(q2, q3, aI1);
                float* d = &g_P[(t - 1) & 3][grp][r][0];
                __stcg(d + (ph * 4 + 0) * 256 + pj, q0);
                __stcg(d + (ph * 4 + 1) * 256 + pj, q1);
                __stcg(d + (ph * 4 + 2) * 256 + pj, q2);
                __stcg(d + (ph * 4 + 3) * 256 + pj, q3);
                signal(f1p);                              // sync inside: WI reads done
            }
            load_slice(u_WI, Wih2 + (long)t * DD * HH + sliceoff, tid);  // Wih2[t]
            CPA_COMMIT();

            // ---- wait peers' partial1[t] (mostly satisfied), combine ----
            waitflag(f1, 4u * (unsigned)(t + 1));
            float sum = pre;
#pragma unroll
            for (int src = 0; src < 4; src++)
                sum += __ldcg(&g_P1[t & 1][grp][src][rowS * 256 + 64 * r + cS]);
            float h1v = tanhf(sum);
            hsO[cS * 8 + rowS] = h1v;
            pre = __ldg(g_pre1 + (long)tn * BB * HH + rmS);
            __syncthreads();                              // hsO ready for next dot
        }
        // epilogue: P[TT-1] = h1[TT-1] @ Wih2[TT-1]
        CPA_WAIT(0);
        __syncthreads();
        ull aI0 = 0ull, aI1 = 0ull;
#pragma unroll
        for (int kl = 0; kl < 64; kl++) {
            ulonglong2 hv = *(const ulonglong2*)(hsO + kl * 8 + 4 * ph);
            float wI = WI[kl * 256 + pj];
            ull wIp = pack2(wI, wI);
            aI0 = fma2(hv.x, wIp, aI0);
            aI1 = fma2(hv.y, wIp, aI1);
        }
        float q0, q1, q2, q3;
        unpack2(q0, q1, aI0);
        unpack2(q2, q3, aI1);
        float* d = &g_P[(TT - 1) & 3][grp][r][0];
        __stcg(d + (ph * 4 + 0) * 256 + pj, q0);
        __stcg(d + (ph * 4 + 1) * 256 + pj, q1);
        __stcg(d + (ph * 4 + 2) * 256 + pj, q2);
        __stcg(d + (ph * 4 + 3) * 256 + pj, q3);
        signal(f1p);
    } else {
        // ============ layer 2: own-cols h2 recurrence ============
        load_slice(u_W0, Whh2 + sliceoff, tid);          // Whh2[0] slice
        CPA_COMMIT();
        for (int i = tid; i < 512; i += NTH) hsO[i] = 0.f;   // h2[-1] own cols = 0
        float biasv = __ldg(b2 + 64 * r + cS);

#pragma unroll 1
        for (int u = 0; u < TT; u++) {
            const int un = (u < TT - 1) ? u + 1 : u;

            CPA_WAIT(0);
            __syncthreads();
            load_slice(((u + 1) & 1) ? u_W1 : u_W0,
                       Whh2 + (long)un * HH * HH + sliceoff, tid);
            CPA_COMMIT();

            const float* sWB = (u & 1) ? W1 : W0;
            ull a0 = 0ull, a1 = 0ull;
#pragma unroll
            for (int kl = 0; kl < 64; kl++) {
                ulonglong2 hv = *(const ulonglong2*)(hsO + kl * 8 + 4 * ph);
                float w = sWB[kl * 256 + pj];
                ull wp = pack2(w, w);
                a0 = fma2(hv.x, wp, a0);
                a1 = fma2(hv.y, wp, a1);
            }
            {   // store partial2[u]
                float q0, q1, q2, q3;
                unpack2(q0, q1, a0);
                unpack2(q2, q3, a1);
                float* dd = &g_P2[u & 1][grp][r][0];
                __stcg(dd + (ph * 4 + 0) * 256 + pj, q0);
                __stcg(dd + (ph * 4 + 1) * 256 + pj, q1);
                __stcg(dd + (ph * 4 + 2) * 256 + pj, q2);
                __stcg(dd + (ph * 4 + 3) * 256 + pj, q3);
            }
            signal(f2);

            // P[u] flag was set by L1 ~a step ago — gather it first (hides f2 wait)
            waitflag(f1p, 4u * (unsigned)(u + 1));
            float pAcc = 0.f;
#pragma unroll
            for (int src = 0; src < 4; src++)
                pAcc += __ldcg(&g_P[u & 3][grp][src][rowS * 256 + 64 * r + cS]);

            waitflag(f2, 4u * (unsigned)(u + 1));
            float acc = biasv + pAcc;
#pragma unroll
            for (int src = 0; src < 4; src++)
                acc += __ldcg(&g_P2[u & 1][grp][src][rowS * 256 + 64 * r + cS]);
            float h2v = tanhf(acc);
            hsO[cS * 8 + rowS] = h2v;
            if (u == TT - 1) g_h2rm[rmS] = h2v;           // final state, row-major
            biasv = __ldg(b2 + (long)un * HH + 64 * r + cS);
            __syncthreads();
        }
    }
}

// ---------------- tail kernels: backward single step + fc head ----------------
__global__ __launch_bounds__(256) void k_tail_a(
    const float* __restrict__ x, const float* __restrict__ Wih_b,
    const float* __restrict__ b_b)
{
    __shared__ float sA[64 * 72];
    __shared__ float sW[64 * 72];
    int tile = blockIdx.x;
    int row0 = (tile >> 2) * 64, col0 = (tile & 3) * 64;
    gemm64_body(x + (long)(TT - 1) * DD, (long)TT * DD,
                nullptr, 1 << 30, 0,
                Wih_b + (long)(TT - 1) * DD * HH, HH, 0,
                b_b + (long)(TT - 1) * HH,
                g_h1bk, HH, DD, row0, col0, /*act=*/1, sA, sW);
}

__global__ __launch_bounds__(256) void k_tail_b(
    const float* __restrict__ Wih_b, const float* __restrict__ b_b)
{
    __shared__ float sA[64 * 72];
    __shared__ float sW[64 * 72];
    int tile = blockIdx.x;
    int row0 = (tile >> 2) * 64, col0 = (tile & 3) * 64;
    gemm64_body(g_h1bk, HH,
                nullptr, 1 << 30, 0,
                Wih_b + (long)(TT + TT - 1) * DD * HH, HH, 0,
                b_b + (long)(TT + TT - 1) * HH,
                g_h2bk, HH, HH, row0, col0, /*act=*/1, sA, sW);
}

__global__ __launch_bounds__(256) void k_tail_c(
    const float* __restrict__ fc_w, const float* __restrict__ fc_b,
    float* __restrict__ out)
{
    __shared__ float sA[64 * 72];
    __shared__ float sW[64 * 72];
    int tile = blockIdx.x;
    int row0 = (tile >> 2) * 64, col0 = (tile & 3) * 64;
    gemm64_body(g_h2rm, HH,
                g_h2bk, /*ksplit=*/HH, HH,
                fc_w, 2 * HH, /*wtrans=*/1,
                fc_b,
                out, HH, 2 * HH, row0, col0, /*act=*/0, sA, sW);
}

// ---------------- launcher (k_seq at profiler capture slot 4) ----------------
extern "C" void kernel_launch(void* const* d_in, const int* in_sizes, int n_in,
                              void* d_out, int out_size) {
    const float* x     = (const float*)d_in[0];
    const float* Wih_f = (const float*)d_in[1];
    const float* Whh_f = (const float*)d_in[2];
    const float* b_f   = (const float*)d_in[3];
    const float* Wih_b = (const float*)d_in[4];
    // d_in[5] = Whh_b: unused (backward output at t=T-1 starts from h0=0)
    const float* b_b   = (const float*)d_in[6];
    const float* fc_w  = (const float*)d_in[7];
    const float* fc_b  = (const float*)d_in[8];
    float* out = (float*)d_out;
    (void)in_sizes; (void)n_in; (void)out_size;

    static_assert(SMEM_SEQ_BYTES == 198656, "smem layout");
    cudaFuncSetAttribute(k_seq, cudaFuncAttributeMaxDynamicSharedMemorySize,
                         SMEM_SEQ_BYTES);

    k_reset<<<2, 256>>>();
    k_pre<<<dim3(8, TT), 256>>>(x, Wih_f, b_f);
    k_tail_a<<<8, 256>>>(x, Wih_b, b_b);
    k_seq<<<NBLK, NTH, SMEM_SEQ_BYTES>>>(Wih_f, Whh_f, b_f);
    k_tail_b<<<8, 256>>>(Wih_b, b_b);
    k_tail_c<<<8, 256>>>(fc_w, fc_b, out);
}

// round 17
// speedup vs baseline: 1.0560x; 1.0560x over previous
#include <cuda_runtime.h>
#include <cuda_bf16.h>
#include <math.h>

// Problem constants
#define BB 128
#define TT 256
#define DD 256
#define HH 256

#define NBLK 128        // 16 groups x 8 CTAs (each CTA runs BOTH layers)
#define NGRP 16
#define NTH  512

typedef unsigned long long ull;

// ---------------- packed f32x2 helpers ----------------
__device__ __forceinline__ ull pack2(float lo, float hi) {
    ull r; asm("mov.b64 %0, {%1, %2};" : "=l"(r) : "f"(lo), "f"(hi)); return r;
}
__device__ __forceinline__ void unpack2(float& lo, float& hi, ull v) {
    asm("mov.b64 {%0, %1}, %2;" : "=f"(lo), "=f"(hi) : "l"(v));
}
__device__ __forceinline__ ull fma2(ull a, ull b, ull c) {
    ull d; asm("fma.rn.f32x2 %0, %1, %2, %3;" : "=l"(d) : "l"(a), "l"(b), "l"(c));
    return d;
}

// ---------------- device scratch ----------------
__device__ float g_pre1[TT * BB * HH];        // pre1[t][b][h] row-major (incl b1)
__device__ float g_p1[2][NGRP][8][2048];      // Whh1 partials [ring2][grp][src][row*256+col]
__device__ float g_gP[2][NGRP][8][2048];      // Wih2 partials
__device__ float g_p2[2][NGRP][8][2048];      // Whh2 partials
__device__ float g_h2rm[BB * HH];             // final forward h2, row-major
__device__ float g_h1bk[BB * HH];
__device__ float g_h2bk[BB * HH];
__device__ unsigned g_f1[NGRP * 32];          // partial1 ready (8 signals/iter)
__device__ unsigned g_fP[NGRP * 32];          // P ready
__device__ unsigned g_f2[NGRP * 32];          // partial2 ready

// ---------------- reset kernel ----------------
__global__ void k_reset() {
    unsigned i = blockIdx.x * blockDim.x + threadIdx.x;
    if (i < NGRP * 32) { g_f1[i] = 0u; g_fP[i] = 0u; g_f2[i] = 0u; }
}

// ---------------- release/acquire flag ops ----------------
__device__ __forceinline__ void signal1(unsigned* p) {
    __syncthreads();
    if (threadIdx.x == 0)
        asm volatile("red.release.gpu.add.u32 [%0], 1;" :: "l"(p) : "memory");
}
__device__ __forceinline__ void signal2(unsigned* pa, unsigned* pb) {
    __syncthreads();
    if (threadIdx.x == 0) {
        asm volatile("red.release.gpu.add.u32 [%0], 1;" :: "l"(pa) : "memory");
        asm volatile("red.release.gpu.add.u32 [%0], 1;" :: "l"(pb) : "memory");
    }
}
__device__ __forceinline__ void waitflag(unsigned* p, unsigned t) {
    if (threadIdx.x == 0) {
        unsigned v;
        do { asm volatile("ld.acquire.gpu.u32 %0, [%1];" : "=r"(v) : "l"(p) : "memory");
        } while (v < t);
    }
    __syncthreads();
}
__device__ __forceinline__ void waitflag2(unsigned* pa, unsigned ta,
                                          unsigned* pb, unsigned tb) {
    if (threadIdx.x == 0) {
        unsigned v;
        do { asm volatile("ld.acquire.gpu.u32 %0, [%1];" : "=r"(v) : "l"(pa) : "memory");
        } while (v < ta);
        do { asm volatile("ld.acquire.gpu.u32 %0, [%1];" : "=r"(v) : "l"(pb) : "memory");
        } while (v < tb);
    }
    __syncthreads();
}

// ---------------- cp.async helpers ----------------
__device__ __forceinline__ unsigned smem_u32(const void* p) {
    unsigned a;
    asm("{ .reg .u64 t; cvta.to.shared.u64 t, %1; cvt.u32.u64 %0, t; }"
        : "=r"(a) : "l"(p));
    return a;
}
__device__ __forceinline__ void cpa16(unsigned saddr, const float* gaddr) {
    asm volatile("cp.async.cg.shared.global [%0], [%1], 16;"
                 :: "r"(saddr), "l"(gaddr) : "memory");
}
#define CPA_COMMIT()  asm volatile("cp.async.commit_group;" ::: "memory")
#define CPA_WAIT(n)   asm volatile("cp.async.wait_group %0;" :: "n"(n) : "memory")

// 32k x 256col weight slice -> smem sW[k*256 + j]; Wbase at slice origin
__device__ __forceinline__ void load_slice32(unsigned u_sW, const float* __restrict__ Wbase,
                                             int tid) {
#pragma unroll
    for (int i = 0; i < 4; i++) {
        int chunk = tid + i * NTH;          // 0..2047 float4 chunks
        int k = chunk >> 6;
        int j4 = (chunk & 63) * 4;
        cpa16(u_sW + (unsigned)chunk * 16, Wbase + (long)k * HH + j4);
    }
}

// ---------------- generic 64x64 register-blocked fp32 GEMM tile (FFMA2) ----------------
__device__ __forceinline__ void gemm64_body(
    const float* __restrict__ A, long lda,
    const float* __restrict__ A2, int ksplit, long lda2,
    const float* __restrict__ W, long ldw, int wtrans,
    const float* __restrict__ bias,
    float* __restrict__ C, long ldc,
    int K, int row0, int col0, int act,
    float* sA, float* sW)
{
    const int tid = threadIdx.x;
    const int tx = tid & 15;
    const int ty = tid >> 4;
    ull accp[4][2];
#pragma unroll
    for (int i = 0; i < 4; i++) { accp[i][0] = 0ull; accp[i][1] = 0ull; }

#pragma unroll 1
    for (int k0 = 0; k0 < K; k0 += 64) {
        const float* Ak = A; long ldak = lda; int kb = k0;
        if (A2 != nullptr && k0 >= ksplit) { Ak = A2; ldak = lda2; kb = k0 - ksplit; }

        __syncthreads();
#pragma unroll
        for (int p = 0; p < 4; p++) {
            int i = p * 256 + tid;
            int rr = i >> 4;
            int k4 = i & 15;
            float4 v = *(const float4*)(Ak + (long)(row0 + rr) * ldak + kb + k4 * 4);
            *(float4*)(sA + rr * 72 + k4 * 4) = v;
        }
        if (!wtrans) {
#pragma unroll
            for (int p = 0; p < 16; p++) {
                int i = p * 256 + tid;
                int kk = i >> 6, cc = i & 63;
                sW[kk * 72 + cc] = W[(long)(k0 + kk) * ldw + col0 + cc];
            }
        } else {
#pragma unroll
            for (int p = 0; p < 16; p++) {
                int i = p * 256 + tid;
                int kk = i & 63, cc = i >> 6;
                sW[kk * 72 + cc] = W[(long)(col0 + cc) * ldw + k0 + kk];
            }
        }
        __syncthreads();

#pragma unroll
        for (int k = 0; k < 64; k++) {
            ulonglong2 wv = *(const ulonglong2*)(sW + k * 72 + tx * 4);
#pragma unroll
            for (int i = 0; i < 4; i++) {
                float a = sA[(ty * 4 + i) * 72 + k];
                ull ap = pack2(a, a);
                accp[i][0] = fma2(ap, wv.x, accp[i][0]);
                accp[i][1] = fma2(ap, wv.y, accp[i][1]);
            }
        }
    }

#pragma unroll
    for (int i = 0; i < 4; i++) {
        float v0, v1, v2, v3;
        unpack2(v0, v1, accp[i][0]);
        unpack2(v2, v3, accp[i][1]);
        float vv[4] = {v0, v1, v2, v3};
#pragma unroll
        for (int j = 0; j < 4; j++) {
            int rr = row0 + ty * 4 + i;
            int cc = col0 + tx * 4 + j;
            float v = vv[j] + bias[cc];
            if (act) v = tanhf(v);
            C[(long)rr * ldc + cc] = v;
        }
    }
}

// ---------------- K1: precompute pre1[t] ----------------
__global__ __launch_bounds__(256) void k_pre(
    const float* __restrict__ x, const float* __restrict__ Wih_f,
    const float* __restrict__ b_f)
{
    __shared__ float sA[64 * 72];
    __shared__ float sW[64 * 72];
    int t = blockIdx.y;
    int tile = blockIdx.x;
    int row0 = (tile >> 2) * 64;
    int col0 = (tile & 3) * 64;
    gemm64_body(x + (long)t * DD, (long)TT * DD,
                nullptr, 1 << 30, 0,
                Wih_f + (long)t * DD * HH, HH, 0,
                b_f + (long)t * HH,
                g_pre1 + (long)t * BB * HH, HH,
                DD, row0, col0, /*act=*/0, sA, sW);
}

// ================= K2: balanced dual-layer k-split scan =================
// Each of the 8 CTAs per group owns 32 columns of BOTH h1 and h2 (h2 lags one
// step). Per iter i (0..TT):
//   dotA+dotP (fused over hsO1=h1[i-1]): partial1[i] (Whh1[i]) + P[i-1] (Wih2[i-1])
//   dotB (over hsO2=h2[i-2]): partial2[i-1] (Whh2[i-1])
//   gather1: h1[i] = tanh(pre1[i] + sum partial1)         [i<TT]
//   gather2: h2[i-1] = tanh(b2[i-1] + sum P + sum p2)     [i>=1]
// FFMA2 floor 1536 cyc (balanced); each flag wait is covered by the other
// layer's dot. Ring2 reuse safety by wait-transitivity (see analysis).

// smem (floats): hsO1 256 | hsO2 256 | A0 8192 | A1 8192 | WI 8192 | WB 8192
#define SMEM_SEQ_BYTES ((512 + 8192 * 4) * 4)

__global__ __launch_bounds__(NTH, 1)
void k_seq(const float* __restrict__ Wih_f, const float* __restrict__ Whh_f,
           const float* __restrict__ b_f)
{
    extern __shared__ float dyn[];
    float* hsO1 = dyn;                  // own h1 cols [kl*8 + row], 32x8
    float* hsO2 = dyn + 256;            // own h2 cols
    float* A0   = dyn + 512;            // Whh1 double buffer 0
    float* A1   = A0 + 8192;            // Whh1 double buffer 1
    float* WI   = A1 + 8192;            // Wih2[i-1] (single)
    float* WB   = WI + 8192;            // Whh2[i-1] (single)
    const unsigned uA0 = smem_u32(A0);
    const unsigned uA1 = smem_u32(A1);
    const unsigned uWI = smem_u32(WI);
    const unsigned uWB = smem_u32(WB);

    const int tid = threadIdx.x;
    const int ph = tid >> 8;                             // dot rows 4ph..4ph+3
    const int pj = tid & 255;                            // dot output col
    const int rowS = (tid >> 5) & 7;                     // gather row (tid<256)
    const int cS = tid & 31;                             // gather own col
    const int grp = blockIdx.x >> 3;
    const int r = blockIdx.x & 7;                        // own cols 32r..32r+31
    const int row_base = grp * 8;
    const int rmS = (row_base + rowS) * HH + 32 * r + cS;
    unsigned* f1 = &g_f1[grp * 32];
    unsigned* fP = &g_fP[grp * 32];
    unsigned* f2 = &g_f2[grp * 32];

    const float* Whh1 = Whh_f;
    const float* Wih2 = Wih_f + (long)TT * DD * HH;
    const float* Whh2 = Whh_f + (long)TT * HH * HH;
    const float* b2   = b_f + (long)TT * HH;
    const long sliceoff = (long)(32 * r) * HH;

    // prologue
    load_slice32(uA0, Whh1 + sliceoff, tid);             // Whh1[0] -> buf0
    CPA_COMMIT();
    for (int i = tid; i < 512; i += NTH) dyn[i] = 0.f;   // h1[-1], h2[-1] = 0
    float pre = (tid < 256) ? __ldg(g_pre1 + rmS) : 0.f;
    float biasv = (tid < 256) ? __ldg(b2 + 32 * r + cS) : 0.f;

#pragma unroll 1
    for (int i = 0; i <= TT; i++) {
        const int ip = i - 1;                            // layer-2 time index
        const int slotA = i & 1;
        const int slotP = ip & 1;                        // (-1)&1 = 1 (garbage slot)
        CPA_WAIT(0);
        __syncthreads();                                 // weights + hsO visible

        // prefetch Whh1[i+1] into the other buffer (used next iter)
        {
            int inx = (i + 1 < TT) ? i + 1 : TT - 1;
            load_slice32(((i + 1) & 1) ? uA1 : uA0,
                         Whh1 + (long)inx * HH * HH + sliceoff, tid);
            CPA_COMMIT();
        }

        // ---- fused dotA (Whh1[i]) + dotP (Wih2[i-1]) over hsO1 ----
        const float* sWA = slotA ? A1 : A0;
        ull aA0 = 0ull, aA1 = 0ull, aI0 = 0ull, aI1 = 0ull;
#pragma unroll
        for (int kl = 0; kl < 32; kl++) {
            ulonglong2 hv = *(const ulonglong2*)(hsO1 + kl * 8 + 4 * ph);
            float wA = sWA[kl * 256 + pj];
            float wI = WI[kl * 256 + pj];
            ull wAp = pack2(wA, wA);
            ull wIp = pack2(wI, wI);
            aA0 = fma2(hv.x, wAp, aA0);
            aA1 = fma2(hv.y, wAp, aA1);
            aI0 = fma2(hv.x, wIp, aI0);
            aI1 = fma2(hv.y, wIp, aI1);
        }
        {
            float q0, q1, q2, q3, s0, s1, s2, s3;
            unpack2(q0, q1, aA0);
            unpack2(q2, q3, aA1);
            unpack2(s0, s1, aI0);
            unpack2(s2, s3, aI1);
            float* d1 = &g_p1[slotA][grp][r][0];
            __stcg(d1 + (ph * 4 + 0) * 256 + pj, q0);
            __stcg(d1 + (ph * 4 + 1) * 256 + pj, q1);
            __stcg(d1 + (ph * 4 + 2) * 256 + pj, q2);
            __stcg(d1 + (ph * 4 + 3) * 256 + pj, q3);
            float* dp = &g_gP[slotP][grp][r][0];
            __stcg(dp + (ph * 4 + 0) * 256 + pj, s0);
            __stcg(dp + (ph * 4 + 1) * 256 + pj, s1);
            __stcg(dp + (ph * 4 + 2) * 256 + pj, s2);
            __stcg(dp + (ph * 4 + 3) * 256 + pj, s3);
        }
        signal2(f1, fP);                                 // sync inside: WI reads done
        {
            int inx = (i < TT) ? i : TT - 1;
            load_slice32(uWI, Wih2 + (long)inx * DD * HH + sliceoff, tid);
            CPA_COMMIT();
        }

        // ---- dotB (Whh2[i-1]) over hsO2 = h2[i-2] ----
        ull b0 = 0ull, b1 = 0ull;
#pragma unroll
        for (int kl = 0; kl < 32; kl++) {
            ulonglong2 hv = *(const ulonglong2*)(hsO2 + kl * 8 + 4 * ph);
            float w = WB[kl * 256 + pj];
            ull wp = pack2(w, w);
            b0 = fma2(hv.x, wp, b0);
            b1 = fma2(hv.y, wp, b1);
        }
        {
            float q0, q1, q2, q3;
            unpack2(q0, q1, b0);
            unpack2(q2, q3, b1);
            float* d2 = &g_p2[slotP][grp][r][0];
            __stcg(d2 + (ph * 4 + 0) * 256 + pj, q0);
            __stcg(d2 + (ph * 4 + 1) * 256 + pj, q1);
            __stcg(d2 + (ph * 4 + 2) * 256 + pj, q2);
            __stcg(d2 + (ph * 4 + 3) * 256 + pj, q3);
        }
        signal1(f2);                                     // sync inside: WB reads done
        {
            int inx = (i < TT) ? i : TT - 1;
            load_slice32(uWB, Whh2 + (long)inx * HH * HH + sliceoff, tid);
            CPA_COMMIT();
        }

        // ---- gather1: h1[i] ----
        if (i < TT) {
            waitflag(f1, 8u * (unsigned)(i + 1));
            if (tid < 256) {
                float sum = pre;
#pragma unroll
                for (int src = 0; src < 8; src++)
                    sum += __ldcg(&g_p1[slotA][grp][src][rowS * 256 + 32 * r + cS]);
                float h1v = tanhf(sum);
                hsO1[cS * 8 + rowS] = h1v;
                int inx = (i + 1 < TT) ? i + 1 : TT - 1;
                pre = __ldg(g_pre1 + (long)inx * BB * HH + rmS);
            }
        }

        // ---- gather2: h2[i-1] ----
        if (i >= 1) {
            waitflag2(fP, 8u * (unsigned)(i + 1), f2, 8u * (unsigned)(i + 1));
            if (tid < 256) {
                float acc = biasv;
#pragma unroll
                for (int src = 0; src < 8; src++)
                    acc += __ldcg(&g_gP[slotP][grp][src][rowS * 256 + 32 * r + cS]);
#pragma unroll
                for (int src = 0; src < 8; src++)
                    acc += __ldcg(&g_p2[slotP][grp][src][rowS * 256 + 32 * r + cS]);
                float h2v = tanhf(acc);
                hsO2[cS * 8 + rowS] = h2v;
                if (ip == TT - 1) g_h2rm[rmS] = h2v;
                int inx = (i < TT) ? i : TT - 1;
                biasv = __ldg(b2 + (long)inx * HH + 32 * r + cS);
            }
        }
    }
}

// ---------------- tail kernels: backward single step + fc head ----------------
__global__ __launch_bounds__(256) void k_tail_a(
    const float* __restrict__ x, const float* __restrict__ Wih_b,
    const float* __restrict__ b_b)
{
    __shared__ float sA[64 * 72];
    __shared__ float sW[64 * 72];
    int tile = blockIdx.x;
    int row0 = (tile >> 2) * 64, col0 = (tile & 3) * 64;
    gemm64_body(x + (long)(TT - 1) * DD, (long)TT * DD,
                nullptr, 1 << 30, 0,
                Wih_b + (long)(TT - 1) * DD * HH, HH, 0,
                b_b + (long)(TT - 1) * HH,
                g_h1bk, HH, DD, row0, col0, /*act=*/1, sA, sW);
}

__global__ __launch_bounds__(256) void k_tail_b(
    const float* __restrict__ Wih_b, const float* __restrict__ b_b)
{
    __shared__ float sA[64 * 72];
    __shared__ float sW[64 * 72];
    int tile = blockIdx.x;
    int row0 = (tile >> 2) * 64, col0 = (tile & 3) * 64;
    gemm64_body(g_h1bk, HH,
                nullptr, 1 << 30, 0,
                Wih_b + (long)(TT + TT - 1) * DD * HH, HH, 0,
                b_b + (long)(TT + TT - 1) * HH,
                g_h2bk, HH, HH, row0, col0, /*act=*/1, sA, sW);
}

__global__ __launch_bounds__(256) void k_tail_c(
    const float* __restrict__ fc_w, const float* __restrict__ fc_b,
    float* __restrict__ out)
{
    __shared__ float sA[64 * 72];
    __shared__ float sW[64 * 72];
    int tile = blockIdx.x;
    int row0 = (tile >> 2) * 64, col0 = (tile & 3) * 64;
    gemm64_body(g_h2rm, HH,
                g_h2bk, /*ksplit=*/HH, HH,
                fc_w, 2 * HH, /*wtrans=*/1,
                fc_b,
                out, HH, 2 * HH, row0, col0, /*act=*/0, sA, sW);
}

// ---------------- launcher (k_seq at profiler capture slot 4) ----------------
extern "C" void kernel_launch(void* const* d_in, const int* in_sizes, int n_in,
                              void* d_out, int out_size) {
    const float* x     = (const float*)d_in[0];
    const float* Wih_f = (const float*)d_in[1];
    const float* Whh_f = (const float*)d_in[2];
    const float* b_f   = (const float*)d_in[3];
    const float* Wih_b = (const float*)d_in[4];
    // d_in[5] = Whh_b: unused (backward output at t=T-1 starts from h0=0)
    const float* b_b   = (const float*)d_in[6];
    const float* fc_w  = (const float*)d_in[7];
    const float* fc_b  = (const float*)d_in[8];
    float* out = (float*)d_out;
    (void)in_sizes; (void)n_in; (void)out_size;

    static_assert(SMEM_SEQ_BYTES == 133120, "smem layout");
    cudaFuncSetAttribute(k_seq, cudaFuncAttributeMaxDynamicSharedMemorySize,
                         SMEM_SEQ_BYTES);

    k_reset<<<2, 256>>>();
    k_pre<<<dim3(8, TT), 256>>>(x, Wih_f, b_f);
    k_tail_a<<<8, 256>>>(x, Wih_b, b_b);
    k_seq<<<NBLK, NTH, SMEM_SEQ_BYTES>>>(Wih_f, Whh_f, b_f);
    k_tail_b<<<8, 256>>>(Wih_b, b_b);
    k_tail_c<<<8, 256>>>(fc_w, fc_b, out);
}